// round 17
// baseline (speedup 1.0000x reference)
#include <cuda_runtime.h>
#include <cuda_fp16.h>
#include <cstdint>

#define MAXN 100000
#define MAXE 600000
#define F1 128
#define F2 64

// Scratch: __device__ globals (allocation-free rule), referenced directly as symbols.
__device__ __half g_h1h[MAXN * F1];   // x @ W1 (fp16, gather operand)
__device__ __half g_h2h[MAXN * F2];   // layer-2 features (fp16, gather operand)
__device__ float  g_dinv[MAXN];       // rsqrt(deg+1)
__device__ int    g_eidx[2 * MAXE];   // normalized int32 edge index [src | dst]
__device__ int    g_is32 = 0;         // != 0 if raw edge buffer is int32 (idempotent)
__device__ int    g_deg[MAXN];        // in-degree; zero at load (BSS), re-zeroed by fill
__device__ int    g_rowptr[MAXN + 1]; // CSR row pointers (by dst)
__device__ int    g_cnt[MAXN];        // fill counters
__device__ int    g_col[MAXE];        // CSR: src per edge
__device__ float  g_wsrc[MAXE];       // CSR: dinv[src] per edge

// ---------------- fp16 mma helper ----------------
__device__ __forceinline__ void mma_f16(float* c, uint32_t a0, uint32_t a1, uint32_t a2,
                                        uint32_t a3, uint32_t b0, uint32_t b1) {
    asm volatile(
        "mma.sync.aligned.m16n8k16.row.col.f32.f16.f16.f32 "
        "{%0,%1,%2,%3}, {%4,%5,%6,%7}, {%8,%9}, {%0,%1,%2,%3};"
        : "+f"(c[0]), "+f"(c[1]), "+f"(c[2]), "+f"(c[3])
        : "r"(a0), "r"(a1), "r"(a2), "r"(a3), "r"(b0), "r"(b1));
}

// ---------------- edge dtype detection (sampled, 1 block) ----------------
__global__ void detect_kernel(const void* __restrict__ ei_raw, int E, int n) {
    const long long* p = (const long long*)ei_raw;
    int stride = E / 512; if (stride < 1) stride = 1;
    int lbad = 0;
    for (int k = threadIdx.x; k < 512; k += blockDim.x) {
        int i = k * stride; if (i >= E) i = E - 1;
        long long v = p[i];
        if (v < 0 || v >= (long long)n) lbad = 1;
    }
    if (__syncthreads_or(lbad) && threadIdx.x == 0) atomicOr(&g_is32, 1);
}

// normalize edges to int32 + count in-degrees (dst half) in one pass
__global__ void convert_kernel(const void* __restrict__ ei_raw, int E, int n) {
    int i = blockIdx.x * blockDim.x + threadIdx.x;
    if (i >= 2 * E) return;
    int v;
    if (g_is32) v = ((const int*)ei_raw)[i];
    else        v = (int)((const long long*)ei_raw)[i];
    v = v < 0 ? 0 : (v >= n ? n - 1 : v);
    g_eidx[i] = v;
    if (i >= E) atomicAdd(&g_deg[v], 1);  // dst half
}

// ---------------- CSR build: single-block scan (rowptr + dinv + cnt in one kernel) ----------------
__global__ void scan_kernel(int n, int E) {
    __shared__ int sums[1024];
    int chunk = (n + 1023) / 1024;
    int t = threadIdx.x;
    int lo = t * chunk;
    int hi = lo + chunk; if (hi > n) hi = n;
    int s = 0;
    for (int i = lo; i < hi; i++) s += g_deg[i];
    sums[t] = s;
    __syncthreads();
    int acc = s;
    for (int off = 1; off < 1024; off <<= 1) {
        int tv = (t >= off) ? sums[t - off] : 0;
        __syncthreads();
        acc += tv;
        sums[t] = acc;
        __syncthreads();
    }
    int run = acc - s;  // exclusive prefix of this chunk
    for (int i = lo; i < hi; i++) {
        int dg = g_deg[i];
        g_rowptr[i] = run;
        run += dg;
        g_dinv[i] = rsqrtf((float)(dg + 1));
        g_cnt[i] = 0;
    }
    if (t == 0) g_rowptr[n] = E;
}

// fill CSR buckets + re-zero g_deg for the next call (deg is dead after scan)
__global__ void fill_kernel(int E, int n) {
    int e = blockIdx.x * blockDim.x + threadIdx.x;
    if (e < n) g_deg[e] = 0;
    if (e >= E) return;
    int s = g_eidx[e];
    int d = g_eidx[E + e];
    int pos = g_rowptr[d] + atomicAdd(&g_cnt[d], 1);
    g_col[pos] = s;
    g_wsrc[pos] = g_dinv[s];
}

// ---------------- GEMM1: fp16 mma (m16n8k16), A = x (fp32), C = g_h1h ----------------
__global__ __launch_bounds__(256)
void gemm1_kernel(const float* __restrict__ Ain, const float* __restrict__ W, int M) {
    constexpr int N = 128, K = 128, BM = 128, BK = 32;
    constexpr int AK2 = BK / 2;     // 16 half2 per A row chunk
    constexpr int ASTR = AK2 + 4;   // 20
    constexpr int WSTR = N + 8;     // 136
    constexpr int NT = N / 8;       // 16

    __shared__ alignas(16) uint32_t As[BM][ASTR];
    __shared__ alignas(16) uint32_t Ws[AK2][WSTR];

    const int tid = threadIdx.x;
    const int warp = tid >> 5;
    const int lane = tid & 31;
    const int gid = lane >> 2;
    const int tig = lane & 3;
    const int row0 = blockIdx.x * BM;

    float acc[NT][4];
#pragma unroll
    for (int nt = 0; nt < NT; nt++)
#pragma unroll
        for (int j = 0; j < 4; j++) acc[nt][j] = 0.0f;

    for (int k0 = 0; k0 < K; k0 += BK) {
#pragma unroll
        for (int i = 0; i < 4; i++) {
            int t = tid + i * 256;
            int r = t >> 3;
            int c4 = t & 7;
            int grow = row0 + r;
            float4 v = make_float4(0.f, 0.f, 0.f, 0.f);
            if (grow < M)
                v = *reinterpret_cast<const float4*>(&Ain[(size_t)grow * K + k0 + c4 * 4]);
            uint2 o;
            *reinterpret_cast<__half2*>(&o.x) = __floats2half2_rn(v.x, v.y);
            *reinterpret_cast<__half2*>(&o.y) = __floats2half2_rn(v.z, v.w);
            *reinterpret_cast<uint2*>(&As[r][c4 * 2]) = o;
        }
#pragma unroll
        for (int i = 0; i < (AK2 * (N / 4)) / 256; i++) {
            int t = tid + i * 256;
            int k2 = t / (N / 4);
            int c4 = t % (N / 4);
            float4 w0 = *reinterpret_cast<const float4*>(&W[(size_t)(k0 + 2 * k2) * N + c4 * 4]);
            float4 w1 = *reinterpret_cast<const float4*>(&W[(size_t)(k0 + 2 * k2 + 1) * N + c4 * 4]);
            uint4 o;
            *reinterpret_cast<__half2*>(&o.x) = __floats2half2_rn(w0.x, w1.x);
            *reinterpret_cast<__half2*>(&o.y) = __floats2half2_rn(w0.y, w1.y);
            *reinterpret_cast<__half2*>(&o.z) = __floats2half2_rn(w0.z, w1.z);
            *reinterpret_cast<__half2*>(&o.w) = __floats2half2_rn(w0.w, w1.w);
            *reinterpret_cast<uint4*>(&Ws[k2][c4 * 4]) = o;
        }
        __syncthreads();

#pragma unroll
        for (int ks = 0; ks < BK / 16; ks++) {
            int base = ks * 8;
            uint32_t a0 = As[warp * 16 + gid][base + tig];
            uint32_t a1 = As[warp * 16 + gid + 8][base + tig];
            uint32_t a2 = As[warp * 16 + gid][base + tig + 4];
            uint32_t a3 = As[warp * 16 + gid + 8][base + tig + 4];
#pragma unroll
            for (int nt = 0; nt < NT; nt++) {
                uint32_t b0 = Ws[base + tig][nt * 8 + gid];
                uint32_t b1 = Ws[base + tig + 4][nt * 8 + gid];
                mma_f16(acc[nt], a0, a1, a2, a3, b0, b1);
            }
        }
        __syncthreads();
    }

    int r0 = row0 + warp * 16 + gid;
    int r1 = r0 + 8;
#pragma unroll
    for (int nt = 0; nt < NT; nt++) {
        int col = nt * 8 + tig * 2;
        if (r0 < M)
            *reinterpret_cast<__half2*>(&g_h1h[(size_t)r0 * N + col]) =
                __floats2half2_rn(acc[nt][0], acc[nt][1]);
        if (r1 < M)
            *reinterpret_cast<__half2*>(&g_h1h[(size_t)r1 * N + col]) =
                __floats2half2_rn(acc[nt][2], acc[nt][3]);
    }
}

// ---------------- FUSED: gather1 + bias/relu + GEMM2 -> g_h2h ----------------
// Block = 128 dst rows. Phase 0: stage W2 (half2 k-packed) + per-lane bias regs.
// Phase 1: warp w gathers dst rows row0+16w+t (t=0..15) from g_h1h via CSR,
//          applies relu(di*(di*h1[d]+sum)+b1), stores fp16 into the A tile.
// Phase 2: m16n8k16 mma over K=128 against W2; epilogue -> g_h2h (fp16).
// Dynamic smem: As[128][68] u32 (34816B) + Ws[64][72] u32 (18432B) = 53248B.
__global__ __launch_bounds__(256)
void fused_g1_gemm2_kernel(const float* __restrict__ W, const float* __restrict__ b1, int M) {
    constexpr int K = 128, N = 64;
    constexpr int ASTR = 68;   // (68*gid+tig)%32 = (4gid+tig) distinct -> conflict-free
    constexpr int WSTR = 72;   // (72*tig+8nt+gid)%32 = (8tig+8nt+gid) distinct
    constexpr int NT = N / 8;  // 8

    extern __shared__ uint32_t dyn[];
    uint32_t (*As)[ASTR] = reinterpret_cast<uint32_t(*)[ASTR]>(dyn);          // [128][68]
    uint32_t (*Ws)[WSTR] = reinterpret_cast<uint32_t(*)[WSTR]>(dyn + 128 * ASTR);  // [64][72]

    const int tid = threadIdx.x;
    const int warp = tid >> 5;
    const int lane = tid & 31;
    const int gid = lane >> 2;
    const int tig = lane & 3;
    const int row0 = blockIdx.x * 128;

    // phase 0: stage W2 (K=128 -> 64 k2-rows), 1024 tasks / 256 threads
#pragma unroll
    for (int i = 0; i < 4; i++) {
        int t = tid + i * 256;
        int k2 = t / (N / 4);
        int c4 = t % (N / 4);
        float4 w0 = *reinterpret_cast<const float4*>(&W[(size_t)(2 * k2) * N + c4 * 4]);
        float4 w1 = *reinterpret_cast<const float4*>(&W[(size_t)(2 * k2 + 1) * N + c4 * 4]);
        uint4 o;
        *reinterpret_cast<__half2*>(&o.x) = __floats2half2_rn(w0.x, w1.x);
        *reinterpret_cast<__half2*>(&o.y) = __floats2half2_rn(w0.y, w1.y);
        *reinterpret_cast<__half2*>(&o.z) = __floats2half2_rn(w0.z, w1.z);
        *reinterpret_cast<__half2*>(&o.w) = __floats2half2_rn(w0.w, w1.w);
        *reinterpret_cast<uint4*>(&Ws[k2][c4 * 4]) = o;
    }
    // per-lane bias (cols 4*lane .. 4*lane+3)
    float4 bv = *reinterpret_cast<const float4*>(&b1[lane * 4]);

    // phase 1: gather 16 dst rows per warp
    for (int t = 0; t < 16; t++) {
        int r = warp * 16 + t;
        int d = row0 + r;
        float rx = 0.f, ry = 0.f, rz = 0.f, rw = 0.f;
        if (d < M) {
            int beg = g_rowptr[d];
            int end = g_rowptr[d + 1];
            float di = g_dinv[d];
            float a0 = 0.f, a1 = 0.f, a2 = 0.f, a3 = 0.f;
            for (int base = beg; base < end; base += 32) {
                int m = end - base;
                if (m > 32) m = 32;
                int idx = 0; float w = 0.f;
                if (lane < m) { idx = g_col[base + lane]; w = g_wsrc[base + lane]; }
                for (int j = 0; j < m; j++) {
                    int s = __shfl_sync(0xffffffffu, idx, j);
                    float ww = __shfl_sync(0xffffffffu, w, j);
                    uint2 u = *reinterpret_cast<const uint2*>(&g_h1h[(size_t)s * K + lane * 4]);
                    float2 f0 = __half22float2(*reinterpret_cast<const __half2*>(&u.x));
                    float2 f1 = __half22float2(*reinterpret_cast<const __half2*>(&u.y));
                    a0 = fmaf(ww, f0.x, a0); a1 = fmaf(ww, f0.y, a1);
                    a2 = fmaf(ww, f1.x, a2); a3 = fmaf(ww, f1.y, a3);
                }
            }
            uint2 u = *reinterpret_cast<const uint2*>(&g_h1h[(size_t)d * K + lane * 4]);
            float2 f0 = __half22float2(*reinterpret_cast<const __half2*>(&u.x));
            float2 f1 = __half22float2(*reinterpret_cast<const __half2*>(&u.y));
            rx = fmaxf(di * fmaf(di, f0.x, a0) + bv.x, 0.f);
            ry = fmaxf(di * fmaf(di, f0.y, a1) + bv.y, 0.f);
            rz = fmaxf(di * fmaf(di, f1.x, a2) + bv.z, 0.f);
            rw = fmaxf(di * fmaf(di, f1.y, a3) + bv.w, 0.f);
        }
        uint2 o;
        *reinterpret_cast<__half2*>(&o.x) = __floats2half2_rn(rx, ry);
        *reinterpret_cast<__half2*>(&o.y) = __floats2half2_rn(rz, rw);
        *reinterpret_cast<uint2*>(&As[r][lane * 2]) = o;
    }
    __syncthreads();

    // phase 2: mma over K=128 (8 k16 steps)
    float acc[NT][4];
#pragma unroll
    for (int nt = 0; nt < NT; nt++)
#pragma unroll
        for (int j = 0; j < 4; j++) acc[nt][j] = 0.0f;

#pragma unroll
    for (int ks = 0; ks < K / 16; ks++) {
        int base = ks * 8;
        uint32_t a0 = As[warp * 16 + gid][base + tig];
        uint32_t a1 = As[warp * 16 + gid + 8][base + tig];
        uint32_t a2 = As[warp * 16 + gid][base + tig + 4];
        uint32_t a3 = As[warp * 16 + gid + 8][base + tig + 4];
#pragma unroll
        for (int nt = 0; nt < NT; nt++) {
            uint32_t b0 = Ws[base + tig][nt * 8 + gid];
            uint32_t b1v = Ws[base + tig + 4][nt * 8 + gid];
            mma_f16(acc[nt], a0, a1, a2, a3, b0, b1v);
        }
    }

    int r0 = row0 + warp * 16 + gid;
    int r1 = r0 + 8;
#pragma unroll
    for (int nt = 0; nt < NT; nt++) {
        int col = nt * 8 + tig * 2;
        if (r0 < M)
            *reinterpret_cast<__half2*>(&g_h2h[(size_t)r0 * N + col]) =
                __floats2half2_rn(acc[nt][0], acc[nt][1]);
        if (r1 < M)
            *reinterpret_cast<__half2*>(&g_h2h[(size_t)r1 * N + col]) =
                __floats2half2_rn(acc[nt][2], acc[nt][3]);
    }
}

// ---------------- gather2: CSR gather over g_h2h -> d_out (fp32, + b2) ----------------
__global__ void gather2_kernel(const float* __restrict__ b2, float* __restrict__ outp, int n) {
    int d = (blockIdx.x * blockDim.x + threadIdx.x) >> 5;
    if (d >= n) return;
    int lane = threadIdx.x & 31;

    int beg = g_rowptr[d];
    int end = g_rowptr[d + 1];
    float di = g_dinv[d];

    float a0 = 0.f, a1 = 0.f;
    for (int base = beg; base < end; base += 32) {
        int m = end - base;
        if (m > 32) m = 32;
        int idx = 0; float w = 0.f;
        if (lane < m) { idx = g_col[base + lane]; w = g_wsrc[base + lane]; }
        for (int j = 0; j < m; j++) {
            int s = __shfl_sync(0xffffffffu, idx, j);
            float ww = __shfl_sync(0xffffffffu, w, j);
            uint32_t u = *reinterpret_cast<const uint32_t*>(&g_h2h[(size_t)s * F2 + lane * 2]);
            float2 f0 = __half22float2(*reinterpret_cast<const __half2*>(&u));
            a0 = fmaf(ww, f0.x, a0); a1 = fmaf(ww, f0.y, a1);
        }
    }

    uint32_t u = *reinterpret_cast<const uint32_t*>(&g_h2h[(size_t)d * F2 + lane * 2]);
    float2 f0 = __half22float2(*reinterpret_cast<const __half2*>(&u));
    float2 b = *reinterpret_cast<const float2*>(&b2[lane * 2]);
    float2 r;
    r.x = di * fmaf(di, f0.x, a0) + b.x;
    r.y = di * fmaf(di, f0.y, a1) + b.y;
    *reinterpret_cast<float2*>(&outp[(size_t)d * F2 + lane * 2]) = r;
}

extern "C" void kernel_launch(void* const* d_in, const int* in_sizes, int n_in,
                              void* d_out, int out_size) {
    const float* x = (const float*)d_in[0];
    const void* ei = d_in[1];
    const float* W1 = (const float*)d_in[2];
    const float* b1 = (const float*)d_in[3];
    const float* W2 = (const float*)d_in[4];
    const float* b2 = (const float*)d_in[5];
    float* out = (float*)d_out;

    const int n = in_sizes[0] / F1;
    const int E = in_sizes[1] / 2;

    const int T = 256;
    const int FUSED_SMEM = (128 * 68 + 64 * 72) * 4;  // 53248 bytes
    cudaFuncSetAttribute(fused_g1_gemm2_kernel,
                         cudaFuncAttributeMaxDynamicSharedMemorySize, FUSED_SMEM);

    // Fork: GEMM1 (x, W1 only) on side stream, concurrent with edge/CSR chain.
    cudaStream_t s2;
    cudaStreamCreateWithFlags(&s2, cudaStreamNonBlocking);
    cudaEvent_t evFork, evJoin;
    cudaEventCreateWithFlags(&evFork, cudaEventDisableTiming);
    cudaEventCreateWithFlags(&evJoin, cudaEventDisableTiming);

    cudaEventRecord(evFork, 0);
    cudaStreamWaitEvent(s2, evFork, 0);
    gemm1_kernel<<<(n + 127) / 128, 256, 0, s2>>>(x, W1, n);
    cudaEventRecord(evJoin, s2);

    // chain A: sampled dtype detect, normalize (+ degree count), scan, fill
    detect_kernel<<<1, T>>>(ei, E, n);
    convert_kernel<<<(2 * E + T - 1) / T, T>>>(ei, E, n);
    scan_kernel<<<1, 1024>>>(n, E);
    fill_kernel<<<(E + T - 1) / T, T>>>(E, n);

    // join: fused kernel needs g_h1h (chain B) and the CSR (chain A)
    cudaStreamWaitEvent(0, evJoin, 0);

    // fused: gather1 + bias/relu + GEMM2 -> g_h2h
    fused_g1_gemm2_kernel<<<(n + 127) / 128, 256, FUSED_SMEM>>>(W2, b1, n);

    // out = D^-1/2 (A+I) D^-1/2 h2 + b2
    gather2_kernel<<<(n * 32 + T - 1) / T, T>>>(b2, out, n);
}